// round 9
// baseline (speedup 1.0000x reference)
#include <cuda_runtime.h>
#include <cuda_bf16.h>
#include <math.h>

// ---------------- problem constants ----------------
#define BATCH 32
#define NTOK  197               // 196 patches + cls
#define TOK   (BATCH*NTOK)      // 6304
#define PTOK  (BATCH*196)       // 6272
#define DIM   768
#define HEADS 12
#define DH    64
#define MLPD  3072
#define NC    1000
#define LAYERS 12
#define QKVD  (3*DIM)           // 2304 fused qkv width

// arena shared by mutually-exclusive phases: im2col patches (pre-loop),
// attention scores (attention phase), MLP intermediate (MLP phase).
// sizes: patch 4.82M, att 14.90M, mlp 19.37M floats -> arena = mlp size
#define ARENA_F (TOK*MLPD)

// ---------------- scratch (device globals; no allocation allowed) ----------------
__device__ __align__(128) float g_arena[ARENA_F];
__device__ __align__(128) float g_x    [TOK*DIM];
__device__ __align__(128) float g_h    [TOK*DIM];
__device__ __align__(128) float g_qkv  [TOK*QKVD];
__device__ __align__(128) float g_o    [TOK*DIM];
__device__ __align__(128) float g_wt   [DIM*DIM];     // transposed patch weight
__device__ __align__(128) float g_wqkv [DIM*QKVD];    // fused qkv weight [K=768, N=2304]
__device__ __align__(128) float g_bqkv [QKVD];
__device__ __align__(128) float g_pool [BATCH*DIM];
__device__ __align__(128) float g_pooln[BATCH*DIM];

// ---------------- helpers ----------------
__device__ __forceinline__ float gelu_tanh(float x) {
    // jax.nn.gelu default (approximate=True)
    float x3 = x * x * x;
    float t  = tanhf(0.7978845608028654f * (x + 0.044715f * x3));
    return 0.5f * x * (1.0f + t);
}

// ---------------- SGEMM: C[M,N] = act(A[M,K] @ B[K,N] + bias) (+ res) ----------------
// 128x128 tile, BK=16, 256 threads, 8x8 per-thread register tile. K must be %16.
__global__ __launch_bounds__(256, 2)
void sgemm128(const float* __restrict__ A, const float* __restrict__ B,
              const float* __restrict__ bias, const float* __restrict__ res,
              float* __restrict__ C, int M, int N, int K, int act)
{
    __shared__ float As[16][128];   // As[k][m]
    __shared__ float Bs[16][128];   // Bs[k][n]

    const int tid = threadIdx.x;
    const int tx  = tid & 15;       // n groups
    const int ty  = tid >> 4;       // m groups
    const int m0  = blockIdx.y * 128;
    const int n0  = blockIdx.x * 128;

    float acc[8][8];
    #pragma unroll
    for (int i = 0; i < 8; i++)
        #pragma unroll
        for (int j = 0; j < 8; j++) acc[i][j] = 0.f;

    for (int k0 = 0; k0 < K; k0 += 16) {
        // A tile: 128 rows x 16 k, stored transposed
        #pragma unroll
        for (int l = 0; l < 2; l++) {
            int e   = tid + 256 * l;        // 0..511
            int row = e >> 2;               // 0..127
            int c4  = (e & 3) * 4;          // 0,4,8,12
            int gm  = m0 + row;
            float4 av = make_float4(0.f, 0.f, 0.f, 0.f);
            if (gm < M) av = *(const float4*)(A + (long)gm * K + k0 + c4);
            As[c4 + 0][row] = av.x;
            As[c4 + 1][row] = av.y;
            As[c4 + 2][row] = av.z;
            As[c4 + 3][row] = av.w;
        }
        // B tile: 16 k-rows x 128 n
        #pragma unroll
        for (int l = 0; l < 2; l++) {
            int e  = tid + 256 * l;
            int r  = e >> 5;                // 0..15
            int c  = (e & 31) * 4;          // 0..124
            int gn = n0 + c;
            const float* src = B + (long)(k0 + r) * N + gn;
            float4 bv;
            if (gn + 3 < N) {
                bv = *(const float4*)src;
            } else {
                bv.x = (gn + 0 < N) ? src[0] : 0.f;
                bv.y = (gn + 1 < N) ? src[1] : 0.f;
                bv.z = (gn + 2 < N) ? src[2] : 0.f;
                bv.w = (gn + 3 < N) ? src[3] : 0.f;
            }
            *(float4*)&Bs[r][c] = bv;
        }
        __syncthreads();

        #pragma unroll
        for (int kk = 0; kk < 16; kk++) {
            float ar[8], br[8];
            *(float4*)&ar[0] = *(const float4*)&As[kk][ty * 4];
            *(float4*)&ar[4] = *(const float4*)&As[kk][64 + ty * 4];
            *(float4*)&br[0] = *(const float4*)&Bs[kk][tx * 4];
            *(float4*)&br[4] = *(const float4*)&Bs[kk][64 + tx * 4];
            #pragma unroll
            for (int i = 0; i < 8; i++)
                #pragma unroll
                for (int j = 0; j < 8; j++)
                    acc[i][j] += ar[i] * br[j];
        }
        __syncthreads();
    }

    #pragma unroll
    for (int i = 0; i < 8; i++) {
        int gm = m0 + ((i < 4) ? (ty * 4 + i) : (64 + ty * 4 + i - 4));
        if (gm >= M) continue;
        #pragma unroll
        for (int j = 0; j < 8; j++) {
            int gn = n0 + ((j < 4) ? (tx * 4 + j) : (64 + tx * 4 + j - 4));
            if (gn >= N) continue;
            float vv = acc[i][j] + bias[gn];
            if (act) vv = gelu_tanh(vv);
            if (res) vv += res[(long)gm * N + gn];
            C[(long)gm * N + gn] = vv;
        }
    }
}

// ---------------- LayerNorm over last dim (=768) ----------------
__global__ void ln_kernel(const float* __restrict__ x, const float* __restrict__ g,
                          const float* __restrict__ b, float* __restrict__ out)
{
    const int row = blockIdx.x;
    const int t   = threadIdx.x;   // 256
    const float* xr = x + (long)row * DIM;

    float v[3];
    float s = 0.f, s2 = 0.f;
    #pragma unroll
    for (int i = 0; i < 3; i++) {
        v[i] = xr[t + 256 * i];
        s  += v[i];
        s2 += v[i] * v[i];
    }
    #pragma unroll
    for (int off = 16; off; off >>= 1) {
        s  += __shfl_down_sync(0xffffffffu, s,  off);
        s2 += __shfl_down_sync(0xffffffffu, s2, off);
    }
    __shared__ float rs[8], rs2[8];
    int wid = t >> 5, lane = t & 31;
    if (lane == 0) { rs[wid] = s; rs2[wid] = s2; }
    __syncthreads();
    if (t == 0) {
        float a = 0.f, c = 0.f;
        #pragma unroll
        for (int i = 0; i < 8; i++) { a += rs[i]; c += rs2[i]; }
        rs[0] = a; rs2[0] = c;
    }
    __syncthreads();
    float mean = rs[0] * (1.f / DIM);
    float var  = rs2[0] * (1.f / DIM) - mean * mean;
    float rstd = rsqrtf(var + 1e-5f);
    float* orow = out + (long)row * DIM;
    #pragma unroll
    for (int i = 0; i < 3; i++) {
        int idx = t + 256 * i;
        orow[idx] = (v[i] - mean) * rstd * g[idx] + b[idx];
    }
}

// ---------------- patch embedding support ----------------
__global__ void im2col_kernel(const float* __restrict__ imgs, float* __restrict__ patches)
{
    long total = (long)PTOK * DIM;
    for (long idx = (long)blockIdx.x * blockDim.x + threadIdx.x; idx < total;
         idx += (long)gridDim.x * blockDim.x) {
        int row = (int)(idx / DIM);     // b*196 + p
        int col = (int)(idx % DIM);     // c*256 + i*16 + j
        int b = row / 196, p = row % 196;
        int ph = p / 14, pw = p % 14;
        int c = col >> 8, rem = col & 255;
        int i = rem >> 4, j = rem & 15;
        patches[idx] = imgs[(((long)(b * 3 + c) * 224) + ph * 16 + i) * 224 + pw * 16 + j];
    }
}

__global__ void transpose768_kernel(const float* __restrict__ w, float* __restrict__ wt)
{
    int idx = blockIdx.x * 256 + threadIdx.x;
    if (idx < DIM * DIM) {
        int d = idx / DIM, k = idx % DIM;
        wt[k * DIM + d] = w[idx];
    }
}

// pack per-layer qkv weights: wqkv[k][n], n<768 -> wq, n<1536 -> wk, else wv
__global__ void qkv_pack_kernel(const float* __restrict__ wq, const float* __restrict__ wk,
                                const float* __restrict__ wv, const float* __restrict__ bq,
                                const float* __restrict__ bk, const float* __restrict__ bv,
                                float* __restrict__ w, float* __restrict__ bias)
{
    int total = DIM * QKVD;
    for (int idx = blockIdx.x * blockDim.x + threadIdx.x; idx < total;
         idx += gridDim.x * blockDim.x) {
        int k = idx / QKVD, n = idx % QKVD;
        int sel = n / DIM, c = n % DIM;
        const float* src = (sel == 0) ? wq : (sel == 1) ? wk : wv;
        w[idx] = src[k * DIM + c];
        if (idx < QKVD) {
            const float* bs = (sel == 0) ? bq : (sel == 1) ? bk : bv;
            bias[idx] = bs[c];
        }
    }
}

// assemble tokens: x[b,0,:] = cls + pos[0]; x[b,1+p,:] = patchembed[b*196+p] + pos[1+p]
__global__ void assemble_kernel(const float* __restrict__ pe, const float* __restrict__ cls,
                                const float* __restrict__ pos, float* __restrict__ x)
{
    long total = (long)TOK * DIM;
    for (long idx = (long)blockIdx.x * blockDim.x + threadIdx.x; idx < total;
         idx += (long)gridDim.x * blockDim.x) {
        int row = (int)(idx / DIM);
        int d   = (int)(idx % DIM);
        int b = row / NTOK, n = row % NTOK;
        float v = (n == 0) ? cls[d] : pe[((long)(b * 196 + n - 1)) * DIM + d];
        x[idx] = v + pos[n * DIM + d];
    }
}

// ---------------- attention (q/k/v live inside fused qkv buffer, row stride QKVD) ----
__global__ void attn_scores_kernel(const float* __restrict__ qkv, float* __restrict__ s)
{
    __shared__ float Qs[16][65], Ks[16][65];
    int bh = blockIdx.z;
    int b = bh / HEADS, hh = bh % HEADS;
    int tx = threadIdx.x, ty = threadIdx.y;
    int tid = ty * 16 + tx;
    int nbase = blockIdx.y * 16, mbase = blockIdx.x * 16;

    #pragma unroll
    for (int l = 0; l < 4; l++) {
        int e = tid + l * 256;          // 0..1023
        int r = e >> 6, d = e & 63;
        int nq = nbase + r;
        Qs[r][d] = (nq < NTOK) ? qkv[((long)(b * NTOK + nq)) * QKVD + hh * DH + d] : 0.f;
        int mk = mbase + r;
        Ks[r][d] = (mk < NTOK) ? qkv[((long)(b * NTOK + mk)) * QKVD + DIM + hh * DH + d] : 0.f;
    }
    __syncthreads();

    float acc = 0.f;
    #pragma unroll
    for (int d = 0; d < DH; d++) acc += Qs[ty][d] * Ks[tx][d];

    int n = nbase + ty, m = mbase + tx;
    if (n < NTOK && m < NTOK)
        s[((long)bh * NTOK + n) * NTOK + m] = acc * 0.125f;
}

// softmax: one warp per row of 197
__global__ void softmax_kernel(float* __restrict__ s, int rows)
{
    int warp = (blockIdx.x * blockDim.x + threadIdx.x) >> 5;
    int lane = threadIdx.x & 31;
    if (warp >= rows) return;
    float* r = s + (long)warp * NTOK;

    float vals[7];
    float mx = -1e30f;
    #pragma unroll
    for (int w = 0; w < 7; w++) {
        int j = lane + 32 * w;
        vals[w] = (j < NTOK) ? r[j] : -1e30f;
        mx = fmaxf(mx, vals[w]);
    }
    #pragma unroll
    for (int off = 16; off; off >>= 1)
        mx = fmaxf(mx, __shfl_xor_sync(0xffffffffu, mx, off));

    float sum = 0.f;
    #pragma unroll
    for (int w = 0; w < 7; w++) {
        int j = lane + 32 * w;
        if (j < NTOK) { vals[w] = expf(vals[w] - mx); sum += vals[w]; }
    }
    #pragma unroll
    for (int off = 16; off; off >>= 1)
        sum += __shfl_xor_sync(0xffffffffu, sum, off);

    float inv = 1.f / sum;
    #pragma unroll
    for (int w = 0; w < 7; w++) {
        int j = lane + 32 * w;
        if (j < NTOK) r[j] = vals[w] * inv;
    }
}

// o[b,n,h,d] = sum_m P[b,h,n,m] * v[b,m,h,d]   (v at offset 2*DIM in qkv rows)
__global__ void attn_av_kernel(const float* __restrict__ s, const float* __restrict__ qkv,
                               float* __restrict__ o)
{
    __shared__ float Ps[16][17], Vs[16][17];
    int bh = blockIdx.z;
    int b = bh / HEADS, hh = bh % HEADS;
    int tx = threadIdx.x, ty = threadIdx.y;
    int n = blockIdx.y * 16 + ty;
    int d = blockIdx.x * 16 + tx;     // d < 64 by grid

    float acc = 0.f;
    for (int mt = 0; mt < 13; mt++) {
        int mP = mt * 16 + tx;
        Ps[ty][tx] = (n < NTOK && mP < NTOK) ? s[((long)bh * NTOK + n) * NTOK + mP] : 0.f;
        int mV = mt * 16 + ty;
        Vs[ty][tx] = (mV < NTOK)
            ? qkv[((long)(b * NTOK + mV)) * QKVD + 2 * DIM + hh * DH + d] : 0.f;
        __syncthreads();
        #pragma unroll
        for (int kk = 0; kk < 16; kk++) acc += Ps[ty][kk] * Vs[kk][tx];
        __syncthreads();
    }
    if (n < NTOK)
        o[((long)(b * NTOK + n)) * DIM + hh * DH + d] = acc;
}

// ---------------- mean pool over tokens ----------------
__global__ void pool_kernel(const float* __restrict__ x, float* __restrict__ out)
{
    int b = blockIdx.x;
    for (int d = threadIdx.x; d < DIM; d += blockDim.x) {
        float s = 0.f;
        for (int n = 0; n < NTOK; n++)
            s += x[((long)(b * NTOK + n)) * DIM + d];
        out[b * DIM + d] = s * (1.f / NTOK);
    }
}

// ---------------- host ----------------
extern "C" void kernel_launch(void* const* d_in, const int* in_sizes, int n_in,
                              void* d_out, int out_size)
{
    const float* imgs    = (const float*)d_in[0];
    const float* patch_w = (const float*)d_in[1];
    const float* patch_b = (const float*)d_in[2];
    const float* cls     = (const float*)d_in[3];
    const float* pos     = (const float*)d_in[4];
    const float* ln1_g   = (const float*)d_in[5];
    const float* ln1_b   = (const float*)d_in[6];
    const float* wq      = (const float*)d_in[7];
    const float* bq      = (const float*)d_in[8];
    const float* wk      = (const float*)d_in[9];
    const float* bk      = (const float*)d_in[10];
    const float* wv      = (const float*)d_in[11];
    const float* bv      = (const float*)d_in[12];
    const float* wo      = (const float*)d_in[13];
    const float* bo      = (const float*)d_in[14];
    const float* ln2_g   = (const float*)d_in[15];
    const float* ln2_b   = (const float*)d_in[16];
    const float* w1      = (const float*)d_in[17];
    const float* b1      = (const float*)d_in[18];
    const float* w2      = (const float*)d_in[19];
    const float* b2      = (const float*)d_in[20];
    const float* hn_g    = (const float*)d_in[21];
    const float* hn_b    = (const float*)d_in[22];
    const float* hw      = (const float*)d_in[23];
    const float* hb      = (const float*)d_in[24];
    float* out = (float*)d_out;

    float *arena, *x, *h, *qkv, *o, *wt, *wqkv, *bqkv, *pool, *pooln;
    cudaGetSymbolAddress((void**)&arena, g_arena);
    cudaGetSymbolAddress((void**)&x,     g_x);
    cudaGetSymbolAddress((void**)&h,     g_h);
    cudaGetSymbolAddress((void**)&qkv,   g_qkv);
    cudaGetSymbolAddress((void**)&o,     g_o);
    cudaGetSymbolAddress((void**)&wt,    g_wt);
    cudaGetSymbolAddress((void**)&wqkv,  g_wqkv);
    cudaGetSymbolAddress((void**)&bqkv,  g_bqkv);
    cudaGetSymbolAddress((void**)&pool,  g_pool);
    cudaGetSymbolAddress((void**)&pooln, g_pooln);

    // phase-exclusive views of the arena
    float* patch = arena;   // pre-loop only
    float* att   = arena;   // attention phase only
    float* mlp   = arena;   // MLP phase only

    auto gemm = [](const float* A, const float* B, const float* bias, const float* res,
                   float* C, int M, int N, int K, int act) {
        dim3 grid((N + 127) / 128, (M + 127) / 128);
        sgemm128<<<grid, 256>>>(A, B, bias, res, C, M, N, K, act);
    };

    // ---- patch embedding ----
    im2col_kernel<<<4096, 256>>>(imgs, patch);
    transpose768_kernel<<<(DIM * DIM + 255) / 256, 256>>>(patch_w, wt);
    gemm(patch, wt, patch_b, nullptr, h, PTOK, DIM, DIM, 0);   // h[PTOK, D]
    assemble_kernel<<<4096, 256>>>(h, cls, pos, x);

    // ---- transformer layers ----
    const int rows_sm = BATCH * HEADS * NTOK;
    for (int i = 0; i < LAYERS; i++) {
        const float* Wo = wo + (long)i * DIM * DIM;
        const float* W1 = w1 + (long)i * DIM * MLPD;
        const float* W2 = w2 + (long)i * MLPD * DIM;

        qkv_pack_kernel<<<2048, 256>>>(wq + (long)i * DIM * DIM, wk + (long)i * DIM * DIM,
                                       wv + (long)i * DIM * DIM, bq + i * DIM,
                                       bk + i * DIM, bv + i * DIM, wqkv, bqkv);

        ln_kernel<<<TOK, 256>>>(x, ln1_g + i * DIM, ln1_b + i * DIM, h);
        gemm(h, wqkv, bqkv, nullptr, qkv, TOK, QKVD, DIM, 0);   // fused q|k|v

        attn_scores_kernel<<<dim3(13, 13, BATCH * HEADS), dim3(16, 16)>>>(qkv, att);
        softmax_kernel<<<(rows_sm * 32 + 255) / 256, 256>>>(att, rows_sm);
        attn_av_kernel<<<dim3(4, 13, BATCH * HEADS), dim3(16, 16)>>>(att, qkv, o);

        gemm(o, Wo, bo + i * DIM, x, x, TOK, DIM, DIM, 0);      // x += o@Wo + bo

        ln_kernel<<<TOK, 256>>>(x, ln2_g + i * DIM, ln2_b + i * DIM, h);
        gemm(h, W1, b1 + i * MLPD, nullptr, mlp, TOK, MLPD, DIM, 1);   // gelu
        gemm(mlp, W2, b2 + i * DIM, x, x, TOK, DIM, MLPD, 0);   // x += ...
    }

    // ---- head ----
    pool_kernel<<<BATCH, 256>>>(x, pool);
    ln_kernel<<<BATCH, 256>>>(pool, hn_g, hn_b, pooln);
    gemm(pooln, hw, hb, nullptr, out, BATCH, NC, DIM, 0);
}

// round 10
// speedup vs baseline: 1.3558x; 1.3558x over previous
#include <cuda_runtime.h>
#include <cuda_bf16.h>
#include <mma.h>
#include <math.h>

using namespace nvcuda;

// ---------------- problem constants ----------------
#define BATCH 32
#define NTOK  197               // 196 patches + cls
#define TOK   (BATCH*NTOK)      // 6304
#define PTOK  (BATCH*196)       // 6272
#define DIM   768
#define HEADS 12
#define DH    64
#define MLPD  3072
#define NC    1000
#define LAYERS 12
#define QKVD  (3*DIM)           // 2304 fused qkv width

// arena shared by mutually-exclusive phases
#define ARENA_F (TOK*MLPD)

// ---------------- scratch (device globals; no allocation allowed) ----------------
__device__ __align__(128) float g_arena[ARENA_F];
__device__ __align__(128) float g_x    [TOK*DIM];
__device__ __align__(128) float g_h    [TOK*DIM];
__device__ __align__(128) float g_qkv  [TOK*QKVD];
__device__ __align__(128) float g_o    [TOK*DIM];
__device__ __align__(128) float g_wt   [DIM*DIM];
__device__ __align__(128) float g_wqkv [DIM*QKVD];
__device__ __align__(128) float g_bqkv [QKVD];
__device__ __align__(128) float g_pool [BATCH*DIM];
__device__ __align__(128) float g_pooln[BATCH*DIM];

// ---------------- helpers ----------------
__device__ __forceinline__ float gelu_tanh(float x) {
    float x3 = x * x * x;
    float t  = tanhf(0.7978845608028654f * (x + 0.044715f * x3));
    return 0.5f * x * (1.0f + t);
}

// =====================================================================
// bf16-split WMMA GEMM: C[M,N] = act(A @ B + bias) (+res)
// Requires N % 128 == 0, K % 16 == 0. M guarded.
// 128x128 tile, BK=16, 256 threads = 8 warps (2 m x 4 n), warp tile 64x32.
// Each fp32 operand split hi/lo bf16; acc = hi*hi + hi*lo + lo*hi (fp32 acc).
// =====================================================================
struct SmemT {
    union {
        struct {
            __nv_bfloat16 Ah[16][136];
            __nv_bfloat16 Al[16][136];
            __nv_bfloat16 Bh[16][136];
            __nv_bfloat16 Bl[16][136];
        } st;
        float C[64][132];
    };
};

__global__ __launch_bounds__(256, 2)
void gemm_bf16x3(const float* __restrict__ A, const float* __restrict__ B,
                 const float* __restrict__ bias, const float* __restrict__ res,
                 float* __restrict__ C, int M, int N, int K, int act)
{
    __shared__ SmemT sm;

    const int tid = threadIdx.x;
    const int m0  = blockIdx.y * 128;
    const int n0  = blockIdx.x * 128;
    const int warp = tid >> 5;
    const int wm = warp & 1;        // 0..1 : 64-row group
    const int wn = warp >> 1;       // 0..3 : 32-col group

    wmma::fragment<wmma::accumulator, 16, 16, 16, float> acc[4][2];
    #pragma unroll
    for (int i = 0; i < 4; i++)
        #pragma unroll
        for (int j = 0; j < 2; j++)
            wmma::fill_fragment(acc[i][j], 0.0f);

    for (int k0 = 0; k0 < K; k0 += 16) {
        // ---- A tile 128 rows x 16 k, stored [k][m] (col-major for wmma A) ----
        #pragma unroll
        for (int l = 0; l < 2; l++) {
            int e   = tid + 256 * l;       // 0..511
            int row = e >> 2;              // 0..127
            int c4  = (e & 3) * 4;         // 0,4,8,12
            int gm  = m0 + row;
            float4 av = make_float4(0.f, 0.f, 0.f, 0.f);
            if (gm < M) av = *(const float4*)(A + (long)gm * K + k0 + c4);
            float vv[4] = {av.x, av.y, av.z, av.w};
            #pragma unroll
            for (int j = 0; j < 4; j++) {
                __nv_bfloat16 h = __float2bfloat16(vv[j]);
                __nv_bfloat16 lo = __float2bfloat16(vv[j] - __bfloat162float(h));
                sm.st.Ah[c4 + j][row] = h;
                sm.st.Al[c4 + j][row] = lo;
            }
        }
        // ---- B tile 16 k-rows x 128 n, stored [k][n] (row-major for wmma B) ----
        #pragma unroll
        for (int l = 0; l < 2; l++) {
            int e  = tid + 256 * l;
            int r  = e >> 5;               // 0..15
            int c  = (e & 31) * 4;         // 0..124
            float4 bv = *(const float4*)(B + (long)(k0 + r) * N + n0 + c);
            float vv[4] = {bv.x, bv.y, bv.z, bv.w};
            #pragma unroll
            for (int j = 0; j < 4; j++) {
                __nv_bfloat16 h = __float2bfloat16(vv[j]);
                __nv_bfloat16 lo = __float2bfloat16(vv[j] - __bfloat162float(h));
                sm.st.Bh[r][c + j] = h;
                sm.st.Bl[r][c + j] = lo;
            }
        }
        __syncthreads();

        // ---- compute ----
        wmma::fragment<wmma::matrix_b, 16, 16, 16, __nv_bfloat16, wmma::row_major> bh[2], bl[2];
        #pragma unroll
        for (int j = 0; j < 2; j++) {
            wmma::load_matrix_sync(bh[j], &sm.st.Bh[0][wn * 32 + j * 16], 136);
            wmma::load_matrix_sync(bl[j], &sm.st.Bl[0][wn * 32 + j * 16], 136);
        }
        #pragma unroll
        for (int i = 0; i < 4; i++) {
            wmma::fragment<wmma::matrix_a, 16, 16, 16, __nv_bfloat16, wmma::col_major> ah, al;
            wmma::load_matrix_sync(ah, &sm.st.Ah[0][wm * 64 + i * 16], 136);
            wmma::load_matrix_sync(al, &sm.st.Al[0][wm * 64 + i * 16], 136);
            #pragma unroll
            for (int j = 0; j < 2; j++) {
                wmma::mma_sync(acc[i][j], ah, bh[j], acc[i][j]);
                wmma::mma_sync(acc[i][j], ah, bl[j], acc[i][j]);
                wmma::mma_sync(acc[i][j], al, bh[j], acc[i][j]);
            }
        }
        __syncthreads();
    }

    // ---- epilogue: two 64-row phases through smem ----
    #pragma unroll
    for (int pm = 0; pm < 2; pm++) {
        if (wm == pm) {
            #pragma unroll
            for (int i = 0; i < 4; i++)
                #pragma unroll
                for (int j = 0; j < 2; j++)
                    wmma::store_matrix_sync(&sm.C[i * 16][wn * 32 + j * 16],
                                            acc[i][j], 132, wmma::mem_row_major);
        }
        __syncthreads();
        #pragma unroll
        for (int l = 0; l < 32; l++) {
            int e   = tid + 256 * l;       // 0..8191
            int row = e >> 7;              // 0..63
            int col = e & 127;
            int gm  = m0 + pm * 64 + row;
            if (gm < M) {
                int gn = n0 + col;
                float vv = sm.C[row][col] + bias[gn];
                if (act) vv = gelu_tanh(vv);
                if (res) vv += res[(long)gm * N + gn];
                C[(long)gm * N + gn] = vv;
            }
        }
        __syncthreads();
    }
}

// ---------------- fp32 SGEMM (head only: M=32, N=1000) ----------------
__global__ __launch_bounds__(256, 2)
void sgemm128(const float* __restrict__ A, const float* __restrict__ B,
              const float* __restrict__ bias, const float* __restrict__ res,
              float* __restrict__ C, int M, int N, int K, int act)
{
    __shared__ float As[16][128];
    __shared__ float Bs[16][128];

    const int tid = threadIdx.x;
    const int tx  = tid & 15;
    const int ty  = tid >> 4;
    const int m0  = blockIdx.y * 128;
    const int n0  = blockIdx.x * 128;

    float acc[8][8];
    #pragma unroll
    for (int i = 0; i < 8; i++)
        #pragma unroll
        for (int j = 0; j < 8; j++) acc[i][j] = 0.f;

    for (int k0 = 0; k0 < K; k0 += 16) {
        #pragma unroll
        for (int l = 0; l < 2; l++) {
            int e   = tid + 256 * l;
            int row = e >> 2;
            int c4  = (e & 3) * 4;
            int gm  = m0 + row;
            float4 av = make_float4(0.f, 0.f, 0.f, 0.f);
            if (gm < M) av = *(const float4*)(A + (long)gm * K + k0 + c4);
            As[c4 + 0][row] = av.x;
            As[c4 + 1][row] = av.y;
            As[c4 + 2][row] = av.z;
            As[c4 + 3][row] = av.w;
        }
        #pragma unroll
        for (int l = 0; l < 2; l++) {
            int e  = tid + 256 * l;
            int r  = e >> 5;
            int c  = (e & 31) * 4;
            int gn = n0 + c;
            const float* src = B + (long)(k0 + r) * N + gn;
            float4 bv;
            if (gn + 3 < N) {
                bv = *(const float4*)src;
            } else {
                bv.x = (gn + 0 < N) ? src[0] : 0.f;
                bv.y = (gn + 1 < N) ? src[1] : 0.f;
                bv.z = (gn + 2 < N) ? src[2] : 0.f;
                bv.w = (gn + 3 < N) ? src[3] : 0.f;
            }
            *(float4*)&Bs[r][c] = bv;
        }
        __syncthreads();

        #pragma unroll
        for (int kk = 0; kk < 16; kk++) {
            float ar[8], br[8];
            *(float4*)&ar[0] = *(const float4*)&As[kk][ty * 4];
            *(float4*)&ar[4] = *(const float4*)&As[kk][64 + ty * 4];
            *(float4*)&br[0] = *(const float4*)&Bs[kk][tx * 4];
            *(float4*)&br[4] = *(const float4*)&Bs[kk][64 + tx * 4];
            #pragma unroll
            for (int i = 0; i < 8; i++)
                #pragma unroll
                for (int j = 0; j < 8; j++)
                    acc[i][j] += ar[i] * br[j];
        }
        __syncthreads();
    }

    #pragma unroll
    for (int i = 0; i < 8; i++) {
        int gm = m0 + ((i < 4) ? (ty * 4 + i) : (64 + ty * 4 + i - 4));
        if (gm >= M) continue;
        #pragma unroll
        for (int j = 0; j < 8; j++) {
            int gn = n0 + ((j < 4) ? (tx * 4 + j) : (64 + tx * 4 + j - 4));
            if (gn >= N) continue;
            float vv = acc[i][j] + bias[gn];
            if (act) vv = gelu_tanh(vv);
            if (res) vv += res[(long)gm * N + gn];
            C[(long)gm * N + gn] = vv;
        }
    }
}

// ---------------- LayerNorm over last dim (=768) ----------------
__global__ void ln_kernel(const float* __restrict__ x, const float* __restrict__ g,
                          const float* __restrict__ b, float* __restrict__ out)
{
    const int row = blockIdx.x;
    const int t   = threadIdx.x;   // 256
    const float* xr = x + (long)row * DIM;

    float v[3];
    float s = 0.f, s2 = 0.f;
    #pragma unroll
    for (int i = 0; i < 3; i++) {
        v[i] = xr[t + 256 * i];
        s  += v[i];
        s2 += v[i] * v[i];
    }
    #pragma unroll
    for (int off = 16; off; off >>= 1) {
        s  += __shfl_down_sync(0xffffffffu, s,  off);
        s2 += __shfl_down_sync(0xffffffffu, s2, off);
    }
    __shared__ float rs[8], rs2[8];
    int wid = t >> 5, lane = t & 31;
    if (lane == 0) { rs[wid] = s; rs2[wid] = s2; }
    __syncthreads();
    if (t == 0) {
        float a = 0.f, c = 0.f;
        #pragma unroll
        for (int i = 0; i < 8; i++) { a += rs[i]; c += rs2[i]; }
        rs[0] = a; rs2[0] = c;
    }
    __syncthreads();
    float mean = rs[0] * (1.f / DIM);
    float var  = rs2[0] * (1.f / DIM) - mean * mean;
    float rstd = rsqrtf(var + 1e-5f);
    float* orow = out + (long)row * DIM;
    #pragma unroll
    for (int i = 0; i < 3; i++) {
        int idx = t + 256 * i;
        orow[idx] = (v[i] - mean) * rstd * g[idx] + b[idx];
    }
}

// ---------------- patch embedding support ----------------
__global__ void im2col_kernel(const float* __restrict__ imgs, float* __restrict__ patches)
{
    long total = (long)PTOK * DIM;
    for (long idx = (long)blockIdx.x * blockDim.x + threadIdx.x; idx < total;
         idx += (long)gridDim.x * blockDim.x) {
        int row = (int)(idx / DIM);
        int col = (int)(idx % DIM);
        int b = row / 196, p = row % 196;
        int ph = p / 14, pw = p % 14;
        int c = col >> 8, rem = col & 255;
        int i = rem >> 4, j = rem & 15;
        patches[idx] = imgs[(((long)(b * 3 + c) * 224) + ph * 16 + i) * 224 + pw * 16 + j];
    }
}

__global__ void transpose768_kernel(const float* __restrict__ w, float* __restrict__ wt)
{
    int idx = blockIdx.x * 256 + threadIdx.x;
    if (idx < DIM * DIM) {
        int d = idx / DIM, k = idx % DIM;
        wt[k * DIM + d] = w[idx];
    }
}

__global__ void qkv_pack_kernel(const float* __restrict__ wq, const float* __restrict__ wk,
                                const float* __restrict__ wv, const float* __restrict__ bq,
                                const float* __restrict__ bk, const float* __restrict__ bv,
                                float* __restrict__ w, float* __restrict__ bias)
{
    int total = DIM * QKVD;
    for (int idx = blockIdx.x * blockDim.x + threadIdx.x; idx < total;
         idx += gridDim.x * blockDim.x) {
        int k = idx / QKVD, n = idx % QKVD;
        int sel = n / DIM, c = n % DIM;
        const float* src = (sel == 0) ? wq : (sel == 1) ? wk : wv;
        w[idx] = src[k * DIM + c];
        if (idx < QKVD) {
            const float* bs = (sel == 0) ? bq : (sel == 1) ? bk : bv;
            bias[idx] = bs[c];
        }
    }
}

__global__ void assemble_kernel(const float* __restrict__ pe, const float* __restrict__ cls,
                                const float* __restrict__ pos, float* __restrict__ x)
{
    long total = (long)TOK * DIM;
    for (long idx = (long)blockIdx.x * blockDim.x + threadIdx.x; idx < total;
         idx += (long)gridDim.x * blockDim.x) {
        int row = (int)(idx / DIM);
        int d   = (int)(idx % DIM);
        int b = row / NTOK, n = row % NTOK;
        float v = (n == 0) ? cls[d] : pe[((long)(b * 196 + n - 1)) * DIM + d];
        x[idx] = v + pos[n * DIM + d];
    }
}

// ---------------- attention (q/k/v live inside fused qkv buffer) ----------------
__global__ void attn_scores_kernel(const float* __restrict__ qkv, float* __restrict__ s)
{
    __shared__ float Qs[16][65], Ks[16][65];
    int bh = blockIdx.z;
    int b = bh / HEADS, hh = bh % HEADS;
    int tx = threadIdx.x, ty = threadIdx.y;
    int tid = ty * 16 + tx;
    int nbase = blockIdx.y * 16, mbase = blockIdx.x * 16;

    #pragma unroll
    for (int l = 0; l < 4; l++) {
        int e = tid + l * 256;
        int r = e >> 6, d = e & 63;
        int nq = nbase + r;
        Qs[r][d] = (nq < NTOK) ? qkv[((long)(b * NTOK + nq)) * QKVD + hh * DH + d] : 0.f;
        int mk = mbase + r;
        Ks[r][d] = (mk < NTOK) ? qkv[((long)(b * NTOK + mk)) * QKVD + DIM + hh * DH + d] : 0.f;
    }
    __syncthreads();

    float acc = 0.f;
    #pragma unroll
    for (int d = 0; d < DH; d++) acc += Qs[ty][d] * Ks[tx][d];

    int n = nbase + ty, m = mbase + tx;
    if (n < NTOK && m < NTOK)
        s[((long)bh * NTOK + n) * NTOK + m] = acc * 0.125f;
}

__global__ void softmax_kernel(float* __restrict__ s, int rows)
{
    int warp = (blockIdx.x * blockDim.x + threadIdx.x) >> 5;
    int lane = threadIdx.x & 31;
    if (warp >= rows) return;
    float* r = s + (long)warp * NTOK;

    float vals[7];
    float mx = -1e30f;
    #pragma unroll
    for (int w = 0; w < 7; w++) {
        int j = lane + 32 * w;
        vals[w] = (j < NTOK) ? r[j] : -1e30f;
        mx = fmaxf(mx, vals[w]);
    }
    #pragma unroll
    for (int off = 16; off; off >>= 1)
        mx = fmaxf(mx, __shfl_xor_sync(0xffffffffu, mx, off));

    float sum = 0.f;
    #pragma unroll
    for (int w = 0; w < 7; w++) {
        int j = lane + 32 * w;
        if (j < NTOK) { vals[w] = expf(vals[w] - mx); sum += vals[w]; }
    }
    #pragma unroll
    for (int off = 16; off; off >>= 1)
        sum += __shfl_xor_sync(0xffffffffu, sum, off);

    float inv = 1.f / sum;
    #pragma unroll
    for (int w = 0; w < 7; w++) {
        int j = lane + 32 * w;
        if (j < NTOK) r[j] = vals[w] * inv;
    }
}

__global__ void attn_av_kernel(const float* __restrict__ s, const float* __restrict__ qkv,
                               float* __restrict__ o)
{
    __shared__ float Ps[16][17], Vs[16][17];
    int bh = blockIdx.z;
    int b = bh / HEADS, hh = bh % HEADS;
    int tx = threadIdx.x, ty = threadIdx.y;
    int n = blockIdx.y * 16 + ty;
    int d = blockIdx.x * 16 + tx;

    float acc = 0.f;
    for (int mt = 0; mt < 13; mt++) {
        int mP = mt * 16 + tx;
        Ps[ty][tx] = (n < NTOK && mP < NTOK) ? s[((long)bh * NTOK + n) * NTOK + mP] : 0.f;
        int mV = mt * 16 + ty;
        Vs[ty][tx] = (mV < NTOK)
            ? qkv[((long)(b * NTOK + mV)) * QKVD + 2 * DIM + hh * DH + d] : 0.f;
        __syncthreads();
        #pragma unroll
        for (int kk = 0; kk < 16; kk++) acc += Ps[ty][kk] * Vs[kk][tx];
        __syncthreads();
    }
    if (n < NTOK)
        o[((long)(b * NTOK + n)) * DIM + hh * DH + d] = acc;
}

// ---------------- mean pool over tokens ----------------
__global__ void pool_kernel(const float* __restrict__ x, float* __restrict__ out)
{
    int b = blockIdx.x;
    for (int d = threadIdx.x; d < DIM; d += blockDim.x) {
        float s = 0.f;
        for (int n = 0; n < NTOK; n++)
            s += x[((long)(b * NTOK + n)) * DIM + d];
        out[b * DIM + d] = s * (1.f / NTOK);
    }
}

// ---------------- host ----------------
extern "C" void kernel_launch(void* const* d_in, const int* in_sizes, int n_in,
                              void* d_out, int out_size)
{
    const float* imgs    = (const float*)d_in[0];
    const float* patch_w = (const float*)d_in[1];
    const float* patch_b = (const float*)d_in[2];
    const float* cls     = (const float*)d_in[3];
    const float* pos     = (const float*)d_in[4];
    const float* ln1_g   = (const float*)d_in[5];
    const float* ln1_b   = (const float*)d_in[6];
    const float* wq      = (const float*)d_in[7];
    const float* bq      = (const float*)d_in[8];
    const float* wk      = (const float*)d_in[9];
    const float* bk      = (const float*)d_in[10];
    const float* wv      = (const float*)d_in[11];
    const float* bv      = (const float*)d_in[12];
    const float* wo      = (const float*)d_in[13];
    const float* bo      = (const float*)d_in[14];
    const float* ln2_g   = (const float*)d_in[15];
    const float* ln2_b   = (const float*)d_in[16];
    const float* w1      = (const float*)d_in[17];
    const float* b1      = (const float*)d_in[18];
    const float* w2      = (const float*)d_in[19];
    const float* b2      = (const float*)d_in[20];
    const float* hn_g    = (const float*)d_in[21];
    const float* hn_b    = (const float*)d_in[22];
    const float* hw      = (const float*)d_in[23];
    const float* hb      = (const float*)d_in[24];
    float* out = (float*)d_out;

    float *arena, *x, *h, *qkv, *o, *wt, *wqkv, *bqkv, *pool, *pooln;
    cudaGetSymbolAddress((void**)&arena, g_arena);
    cudaGetSymbolAddress((void**)&x,     g_x);
    cudaGetSymbolAddress((void**)&h,     g_h);
    cudaGetSymbolAddress((void**)&qkv,   g_qkv);
    cudaGetSymbolAddress((void**)&o,     g_o);
    cudaGetSymbolAddress((void**)&wt,    g_wt);
    cudaGetSymbolAddress((void**)&wqkv,  g_wqkv);
    cudaGetSymbolAddress((void**)&bqkv,  g_bqkv);
    cudaGetSymbolAddress((void**)&pool,  g_pool);
    cudaGetSymbolAddress((void**)&pooln, g_pooln);

    // phase-exclusive views of the arena
    float* patch = arena;
    float* att   = arena;
    float* mlp   = arena;

    // tensor-core GEMM (N%128==0, K%16==0)
    auto gemmT = [](const float* A, const float* B, const float* bias, const float* res,
                    float* C, int M, int N, int K, int act) {
        dim3 grid(N / 128, (M + 127) / 128);
        gemm_bf16x3<<<grid, 256>>>(A, B, bias, res, C, M, N, K, act);
    };

    // ---- patch embedding ----
    im2col_kernel<<<4096, 256>>>(imgs, patch);
    transpose768_kernel<<<(DIM * DIM + 255) / 256, 256>>>(patch_w, wt);
    gemmT(patch, wt, patch_b, nullptr, h, PTOK, DIM, DIM, 0);
    assemble_kernel<<<4096, 256>>>(h, cls, pos, x);

    // ---- transformer layers ----
    const int rows_sm = BATCH * HEADS * NTOK;
    for (int i = 0; i < LAYERS; i++) {
        const float* Wo = wo + (long)i * DIM * DIM;
        const float* W1 = w1 + (long)i * DIM * MLPD;
        const float* W2 = w2 + (long)i * MLPD * DIM;

        qkv_pack_kernel<<<2048, 256>>>(wq + (long)i * DIM * DIM, wk + (long)i * DIM * DIM,
                                       wv + (long)i * DIM * DIM, bq + i * DIM,
                                       bk + i * DIM, bv + i * DIM, wqkv, bqkv);

        ln_kernel<<<TOK, 256>>>(x, ln1_g + i * DIM, ln1_b + i * DIM, h);
        gemmT(h, wqkv, bqkv, nullptr, qkv, TOK, QKVD, DIM, 0);

        attn_scores_kernel<<<dim3(13, 13, BATCH * HEADS), dim3(16, 16)>>>(qkv, att);
        softmax_kernel<<<(rows_sm * 32 + 255) / 256, 256>>>(att, rows_sm);
        attn_av_kernel<<<dim3(4, 13, BATCH * HEADS), dim3(16, 16)>>>(att, qkv, o);

        gemmT(o, Wo, bo + i * DIM, x, x, TOK, DIM, DIM, 0);

        ln_kernel<<<TOK, 256>>>(x, ln2_g + i * DIM, ln2_b + i * DIM, h);
        gemmT(h, W1, b1 + i * MLPD, nullptr, mlp, TOK, MLPD, DIM, 1);
        gemmT(mlp, W2, b2 + i * DIM, x, x, TOK, DIM, MLPD, 0);
    }

    // ---- head (fp32 path: N=1000 not a multiple of 128) ----
    pool_kernel<<<BATCH, 256>>>(x, pool);
    ln_kernel<<<BATCH, 256>>>(pool, hn_g, hn_b, pooln);
    {
        dim3 grid((NC + 127) / 128, (BATCH + 127) / 128);
        sgemm128<<<grid, 256>>>(pooln, hw, hb, nullptr, out, BATCH, NC, DIM, 0);
    }
}

// round 11
// speedup vs baseline: 1.5742x; 1.1610x over previous
#include <cuda_runtime.h>
#include <cuda_bf16.h>
#include <cuda_pipeline.h>
#include <mma.h>
#include <math.h>

using namespace nvcuda;

// ---------------- problem constants ----------------
#define BATCH 32
#define NTOK  197               // 196 patches + cls
#define TOK   (BATCH*NTOK)      // 6304
#define PTOK  (BATCH*196)       // 6272
#define DIM   768
#define HEADS 12
#define DH    64
#define MLPD  3072
#define NC    1000
#define LAYERS 12
#define QKVD  (3*DIM)           // 2304 fused qkv width

typedef __nv_bfloat16 bf16;

// ---------------- scratch (device globals; no allocation allowed) ----------------
__device__ __align__(128) float g_att  [BATCH*HEADS*NTOK*NTOK];   // 59.6 MB
__device__ __align__(128) float g_x    [TOK*DIM];
__device__ __align__(128) float g_qkv  [TOK*QKVD];                // also patch-embed f32 out
__device__ __align__(128) float g_bqkv [QKVD];
__device__ __align__(128) float g_pool [BATCH*DIM];
__device__ __align__(128) float g_pooln[BATCH*DIM];
// bf16 hi/lo split buffers
__device__ __align__(128) bf16 g_hh [TOK*DIM],   g_hl [TOK*DIM];     // LN outputs
__device__ __align__(128) bf16 g_oh [TOK*DIM],   g_ol [TOK*DIM];     // attention out
__device__ __align__(128) bf16 g_mh [TOK*MLPD],  g_ml [TOK*MLPD];    // mlp1 out
__device__ __align__(128) bf16 g_ph [PTOK*DIM],  g_pl [PTOK*DIM];    // im2col patches
__device__ __align__(128) bf16 g_wth[DIM*DIM],   g_wtl[DIM*DIM];     // patch weight^T
__device__ __align__(128) bf16 g_wqh[DIM*QKVD],  g_wql[DIM*QKVD];    // fused qkv weight
__device__ __align__(128) bf16 g_woh[DIM*DIM],   g_wol[DIM*DIM];
__device__ __align__(128) bf16 g_w1h[DIM*MLPD],  g_w1l[DIM*MLPD];
__device__ __align__(128) bf16 g_w2h[MLPD*DIM],  g_w2l[MLPD*DIM];

// ---------------- helpers ----------------
__device__ __forceinline__ float gelu_tanh(float x) {
    float x3 = x * x * x;
    float t  = tanhf(0.7978845608028654f * (x + 0.044715f * x3));
    return 0.5f * x * (1.0f + t);
}
__device__ __forceinline__ void split2(float v, bf16& h, bf16& l) {
    h = __float2bfloat16(v);
    l = __float2bfloat16(v - __bfloat162float(h));
}

// =====================================================================
// bf16-split GEMM, pre-split operands, cp.async double buffered.
// C = act(Ah@Bh + Al@Bh + Ah@Bl + bias). N%128==0, K%16==0, M guarded.
// 128x128 tile, BK=16, 2 stages, 256 thr = 8 warps (2m x 4n), warp 64x32.
// mode 0: C(f32) = sum + bias (+res).  mode 1: gelu -> split to Ch/Cl.
// =====================================================================
struct GS {
    union {
        struct {
            bf16 Ah[2][128][24];   // [stage][m][k] row-major, pad 24
            bf16 Al[2][128][24];
            bf16 Bh[2][16][136];   // [stage][k][n] row-major, pad 136
            bf16 Bl[2][16][136];
        } st;                      // 41984 B
        float C[64][132];          // 33792 B epilogue bounce
    };
};

__global__ __launch_bounds__(256, 2)
void gemm_bf16s(const bf16* __restrict__ Ah, const bf16* __restrict__ Al,
                const bf16* __restrict__ Bh, const bf16* __restrict__ Bl,
                const float* __restrict__ bias, const float* __restrict__ res,
                float* __restrict__ C, bf16* __restrict__ Ch, bf16* __restrict__ Cl,
                int M, int N, int K, int mode)
{
    __shared__ GS sm;
    const int tid  = threadIdx.x;
    const int m0   = blockIdx.y * 128;
    const int n0   = blockIdx.x * 128;
    const int warp = tid >> 5;
    const int wm   = warp & 1;           // 0..1 -> 64-row half
    const int wn   = warp >> 1;          // 0..3 -> 32-col group

    // cp.async assignments (16B chunks)
    const int arow = tid >> 1,  achk = (tid & 1) * 8;    // A: 128 rows x 2 chunks
    const int brow = tid >> 4,  bchk = (tid & 15) * 8;   // B: 16 rows x 16 chunks
    const bool ap  = (m0 + arow) < M;
    const long abase = ap ? ((long)(m0 + arow) * K + achk) : 0;
    const size_t az  = ap ? 0 : 16;      // zero-fill when row OOB

    wmma::fragment<wmma::accumulator, 16, 16, 16, float> acc[4][2];
    #pragma unroll
    for (int i = 0; i < 4; i++)
        #pragma unroll
        for (int j = 0; j < 2; j++)
            wmma::fill_fragment(acc[i][j], 0.0f);

    const int KT = K >> 4;

    // prologue: stage 0
    {
        __pipeline_memcpy_async(&sm.st.Ah[0][arow][achk], Ah + abase, 16, az);
        __pipeline_memcpy_async(&sm.st.Al[0][arow][achk], Al + abase, 16, az);
        const long boff = (long)brow * N + n0 + bchk;
        __pipeline_memcpy_async(&sm.st.Bh[0][brow][bchk], Bh + boff, 16, 0);
        __pipeline_memcpy_async(&sm.st.Bl[0][brow][bchk], Bl + boff, 16, 0);
        __pipeline_commit();
    }

    for (int kt = 0; kt < KT; kt++) {
        const int cur = kt & 1;
        if (kt + 1 < KT) {
            const int nxt = (kt + 1) & 1;
            const int k0  = (kt + 1) << 4;
            __pipeline_memcpy_async(&sm.st.Ah[nxt][arow][achk], Ah + abase + (ap ? k0 : 0), 16, az);
            __pipeline_memcpy_async(&sm.st.Al[nxt][arow][achk], Al + abase + (ap ? k0 : 0), 16, az);
            const long boff = (long)(k0 + brow) * N + n0 + bchk;
            __pipeline_memcpy_async(&sm.st.Bh[nxt][brow][bchk], Bh + boff, 16, 0);
            __pipeline_memcpy_async(&sm.st.Bl[nxt][brow][bchk], Bl + boff, 16, 0);
            __pipeline_commit();
            __pipeline_wait_prior(1);
        } else {
            __pipeline_wait_prior(0);
        }
        __syncthreads();

        wmma::fragment<wmma::matrix_b, 16, 16, 16, bf16, wmma::row_major> fbh[2], fbl[2];
        #pragma unroll
        for (int j = 0; j < 2; j++) {
            wmma::load_matrix_sync(fbh[j], &sm.st.Bh[cur][0][wn * 32 + j * 16], 136);
            wmma::load_matrix_sync(fbl[j], &sm.st.Bl[cur][0][wn * 32 + j * 16], 136);
        }
        #pragma unroll
        for (int i = 0; i < 4; i++) {
            wmma::fragment<wmma::matrix_a, 16, 16, 16, bf16, wmma::row_major> fah, fal;
            wmma::load_matrix_sync(fah, &sm.st.Ah[cur][wm * 64 + i * 16][0], 24);
            wmma::load_matrix_sync(fal, &sm.st.Al[cur][wm * 64 + i * 16][0], 24);
            #pragma unroll
            for (int j = 0; j < 2; j++) {
                wmma::mma_sync(acc[i][j], fah, fbh[j], acc[i][j]);
                wmma::mma_sync(acc[i][j], fal, fbh[j], acc[i][j]);
                wmma::mma_sync(acc[i][j], fah, fbl[j], acc[i][j]);
            }
        }
        __syncthreads();
    }

    // epilogue: two 64-row phases through smem
    #pragma unroll
    for (int pm = 0; pm < 2; pm++) {
        if (wm == pm) {
            #pragma unroll
            for (int i = 0; i < 4; i++)
                #pragma unroll
                for (int j = 0; j < 2; j++)
                    wmma::store_matrix_sync(&sm.C[i * 16][wn * 32 + j * 16],
                                            acc[i][j], 132, wmma::mem_row_major);
        }
        __syncthreads();
        #pragma unroll
        for (int l = 0; l < 32; l++) {
            int e   = tid + 256 * l;
            int row = e >> 7;
            int col = e & 127;
            int gm  = m0 + pm * 64 + row;
            if (gm < M) {
                int gn = n0 + col;
                float vv = sm.C[row][col] + bias[gn];
                if (mode == 1) {
                    vv = gelu_tanh(vv);
                    bf16 h, lo; split2(vv, h, lo);
                    Ch[(long)gm * N + gn] = h;
                    Cl[(long)gm * N + gn] = lo;
                } else {
                    if (res) vv += res[(long)gm * N + gn];
                    C[(long)gm * N + gn] = vv;
                }
            }
        }
        __syncthreads();
    }
}

// ---------------- fp32 SGEMM (head only: M=32, N=1000) ----------------
__global__ __launch_bounds__(256, 2)
void sgemm128(const float* __restrict__ A, const float* __restrict__ B,
              const float* __restrict__ bias, float* __restrict__ C,
              int M, int N, int K)
{
    __shared__ float As[16][128];
    __shared__ float Bs[16][128];

    const int tid = threadIdx.x;
    const int tx  = tid & 15;
    const int ty  = tid >> 4;
    const int m0  = blockIdx.y * 128;
    const int n0  = blockIdx.x * 128;

    float acc[8][8];
    #pragma unroll
    for (int i = 0; i < 8; i++)
        #pragma unroll
        for (int j = 0; j < 8; j++) acc[i][j] = 0.f;

    for (int k0 = 0; k0 < K; k0 += 16) {
        #pragma unroll
        for (int l = 0; l < 2; l++) {
            int e   = tid + 256 * l;
            int row = e >> 2;
            int c4  = (e & 3) * 4;
            int gm  = m0 + row;
            float4 av = make_float4(0.f, 0.f, 0.f, 0.f);
            if (gm < M) av = *(const float4*)(A + (long)gm * K + k0 + c4);
            As[c4 + 0][row] = av.x;
            As[c4 + 1][row] = av.y;
            As[c4 + 2][row] = av.z;
            As[c4 + 3][row] = av.w;
        }
        #pragma unroll
        for (int l = 0; l < 2; l++) {
            int e  = tid + 256 * l;
            int r  = e >> 5;
            int c  = (e & 31) * 4;
            int gn = n0 + c;
            const float* src = B + (long)(k0 + r) * N + gn;
            float4 bv;
            if (gn + 3 < N) {
                bv = *(const float4*)src;
            } else {
                bv.x = (gn + 0 < N) ? src[0] : 0.f;
                bv.y = (gn + 1 < N) ? src[1] : 0.f;
                bv.z = (gn + 2 < N) ? src[2] : 0.f;
                bv.w = (gn + 3 < N) ? src[3] : 0.f;
            }
            *(float4*)&Bs[r][c] = bv;
        }
        __syncthreads();

        #pragma unroll
        for (int kk = 0; kk < 16; kk++) {
            float ar[8], br[8];
            *(float4*)&ar[0] = *(const float4*)&As[kk][ty * 4];
            *(float4*)&ar[4] = *(const float4*)&As[kk][64 + ty * 4];
            *(float4*)&br[0] = *(const float4*)&Bs[kk][tx * 4];
            *(float4*)&br[4] = *(const float4*)&Bs[kk][64 + tx * 4];
            #pragma unroll
            for (int i = 0; i < 8; i++)
                #pragma unroll
                for (int j = 0; j < 8; j++)
                    acc[i][j] += ar[i] * br[j];
        }
        __syncthreads();
    }

    #pragma unroll
    for (int i = 0; i < 8; i++) {
        int gm = m0 + ((i < 4) ? (ty * 4 + i) : (64 + ty * 4 + i - 4));
        if (gm >= M) continue;
        #pragma unroll
        for (int j = 0; j < 8; j++) {
            int gn = n0 + ((j < 4) ? (tx * 4 + j) : (64 + tx * 4 + j - 4));
            if (gn >= N) continue;
            C[(long)gm * N + gn] = acc[i][j] + bias[gn];
        }
    }
}

// ---------------- LayerNorm -> bf16 hi/lo split output ----------------
__global__ void ln_split_kernel(const float* __restrict__ x, const float* __restrict__ g,
                                const float* __restrict__ b,
                                bf16* __restrict__ oh, bf16* __restrict__ ol)
{
    const int row = blockIdx.x;
    const int t   = threadIdx.x;   // 256
    const float* xr = x + (long)row * DIM;

    float v[3];
    float s = 0.f, s2 = 0.f;
    #pragma unroll
    for (int i = 0; i < 3; i++) {
        v[i] = xr[t + 256 * i];
        s  += v[i];
        s2 += v[i] * v[i];
    }
    #pragma unroll
    for (int off = 16; off; off >>= 1) {
        s  += __shfl_down_sync(0xffffffffu, s,  off);
        s2 += __shfl_down_sync(0xffffffffu, s2, off);
    }
    __shared__ float rs[8], rs2[8];
    int wid = t >> 5, lane = t & 31;
    if (lane == 0) { rs[wid] = s; rs2[wid] = s2; }
    __syncthreads();
    if (t == 0) {
        float a = 0.f, c = 0.f;
        #pragma unroll
        for (int i = 0; i < 8; i++) { a += rs[i]; c += rs2[i]; }
        rs[0] = a; rs2[0] = c;
    }
    __syncthreads();
    float mean = rs[0] * (1.f / DIM);
    float var  = rs2[0] * (1.f / DIM) - mean * mean;
    float rstd = rsqrtf(var + 1e-5f);
    #pragma unroll
    for (int i = 0; i < 3; i++) {
        int idx = t + 256 * i;
        float vv = (v[i] - mean) * rstd * g[idx] + b[idx];
        bf16 h, lo; split2(vv, h, lo);
        oh[(long)row * DIM + idx] = h;
        ol[(long)row * DIM + idx] = lo;
    }
}

// ---------------- LayerNorm fp32 out (head) ----------------
__global__ void ln_kernel(const float* __restrict__ x, const float* __restrict__ g,
                          const float* __restrict__ b, float* __restrict__ out)
{
    const int row = blockIdx.x;
    const int t   = threadIdx.x;
    const float* xr = x + (long)row * DIM;

    float v[3];
    float s = 0.f, s2 = 0.f;
    #pragma unroll
    for (int i = 0; i < 3; i++) {
        v[i] = xr[t + 256 * i];
        s  += v[i];
        s2 += v[i] * v[i];
    }
    #pragma unroll
    for (int off = 16; off; off >>= 1) {
        s  += __shfl_down_sync(0xffffffffu, s,  off);
        s2 += __shfl_down_sync(0xffffffffu, s2, off);
    }
    __shared__ float rs[8], rs2[8];
    int wid = t >> 5, lane = t & 31;
    if (lane == 0) { rs[wid] = s; rs2[wid] = s2; }
    __syncthreads();
    if (t == 0) {
        float a = 0.f, c = 0.f;
        #pragma unroll
        for (int i = 0; i < 8; i++) { a += rs[i]; c += rs2[i]; }
        rs[0] = a; rs2[0] = c;
    }
    __syncthreads();
    float mean = rs[0] * (1.f / DIM);
    float var  = rs2[0] * (1.f / DIM) - mean * mean;
    float rstd = rsqrtf(var + 1e-5f);
    float* orow = out + (long)row * DIM;
    #pragma unroll
    for (int i = 0; i < 3; i++) {
        int idx = t + 256 * i;
        orow[idx] = (v[i] - mean) * rstd * g[idx] + b[idx];
    }
}

// ---------------- generic fp32 -> bf16 hi/lo split ----------------
__global__ void split_kernel(const float* __restrict__ s, bf16* __restrict__ h,
                             bf16* __restrict__ l, int n)
{
    for (int i = blockIdx.x * blockDim.x + threadIdx.x; i < n; i += gridDim.x * blockDim.x) {
        bf16 hh, ll; split2(s[i], hh, ll);
        h[i] = hh; l[i] = ll;
    }
}

// ---------------- patch embedding support ----------------
__global__ void im2col_split_kernel(const float* __restrict__ imgs,
                                    bf16* __restrict__ ph, bf16* __restrict__ pl)
{
    long total = (long)PTOK * DIM;
    for (long idx = (long)blockIdx.x * blockDim.x + threadIdx.x; idx < total;
         idx += (long)gridDim.x * blockDim.x) {
        int row = (int)(idx / DIM);
        int col = (int)(idx % DIM);
        int b = row / 196, p = row % 196;
        int phh = p / 14, pw = p % 14;
        int c = col >> 8, rem = col & 255;
        int i = rem >> 4, j = rem & 15;
        float v = imgs[(((long)(b * 3 + c) * 224) + phh * 16 + i) * 224 + pw * 16 + j];
        bf16 h, lo; split2(v, h, lo);
        ph[idx] = h; pl[idx] = lo;
    }
}

__global__ void transpose768_split_kernel(const float* __restrict__ w,
                                          bf16* __restrict__ wh, bf16* __restrict__ wl)
{
    int idx = blockIdx.x * 256 + threadIdx.x;
    if (idx < DIM * DIM) {
        int d = idx / DIM, k = idx % DIM;
        bf16 h, lo; split2(w[idx], h, lo);
        wh[k * DIM + d] = h; wl[k * DIM + d] = lo;
    }
}

// pack per-layer qkv weights (split) + bias
__global__ void qkv_pack_split_kernel(const float* __restrict__ wq, const float* __restrict__ wk,
                                      const float* __restrict__ wv, const float* __restrict__ bq,
                                      const float* __restrict__ bk, const float* __restrict__ bv,
                                      bf16* __restrict__ wh, bf16* __restrict__ wl,
                                      float* __restrict__ bias)
{
    int total = DIM * QKVD;
    for (int idx = blockIdx.x * blockDim.x + threadIdx.x; idx < total;
         idx += gridDim.x * blockDim.x) {
        int k = idx / QKVD, n = idx % QKVD;
        int sel = n / DIM, c = n % DIM;
        const float* src = (sel == 0) ? wq : (sel == 1) ? wk : wv;
        bf16 h, lo; split2(src[k * DIM + c], h, lo);
        wh[idx] = h; wl[idx] = lo;
        if (idx < QKVD) {
            const float* bs = (sel == 0) ? bq : (sel == 1) ? bk : bv;
            bias[idx] = bs[c];
        }
    }
}

// assemble tokens
__global__ void assemble_kernel(const float* __restrict__ pe, const float* __restrict__ cls,
                                const float* __restrict__ pos, float* __restrict__ x)
{
    long total = (long)TOK * DIM;
    for (long idx = (long)blockIdx.x * blockDim.x + threadIdx.x; idx < total;
         idx += (long)gridDim.x * blockDim.x) {
        int row = (int)(idx / DIM);
        int d   = (int)(idx % DIM);
        int b = row / NTOK, n = row % NTOK;
        float v = (n == 0) ? cls[d] : pe[((long)(b * 196 + n - 1)) * DIM + d];
        x[idx] = v + pos[n * DIM + d];
    }
}

// ---------------- attention (q/k/v inside fused qkv buffer) ----------------
__global__ void attn_scores_kernel(const float* __restrict__ qkv, float* __restrict__ s)
{
    __shared__ float Qs[16][65], Ks[16][65];
    int bh = blockIdx.z;
    int b = bh / HEADS, hh = bh % HEADS;
    int tx = threadIdx.x, ty = threadIdx.y;
    int tid = ty * 16 + tx;
    int nbase = blockIdx.y * 16, mbase = blockIdx.x * 16;

    #pragma unroll
    for (int l = 0; l < 4; l++) {
        int e = tid + l * 256;
        int r = e >> 6, d = e & 63;
        int nq = nbase + r;
        Qs[r][d] = (nq < NTOK) ? qkv[((long)(b * NTOK + nq)) * QKVD + hh * DH + d] : 0.f;
        int mk = mbase + r;
        Ks[r][d] = (mk < NTOK) ? qkv[((long)(b * NTOK + mk)) * QKVD + DIM + hh * DH + d] : 0.f;
    }
    __syncthreads();

    float acc = 0.f;
    #pragma unroll
    for (int d = 0; d < DH; d++) acc += Qs[ty][d] * Ks[tx][d];

    int n = nbase + ty, m = mbase + tx;
    if (n < NTOK && m < NTOK)
        s[((long)bh * NTOK + n) * NTOK + m] = acc * 0.125f;
}

__global__ void softmax_kernel(float* __restrict__ s, int rows)
{
    int warp = (blockIdx.x * blockDim.x + threadIdx.x) >> 5;
    int lane = threadIdx.x & 31;
    if (warp >= rows) return;
    float* r = s + (long)warp * NTOK;

    float vals[7];
    float mx = -1e30f;
    #pragma unroll
    for (int w = 0; w < 7; w++) {
        int j = lane + 32 * w;
        vals[w] = (j < NTOK) ? r[j] : -1e30f;
        mx = fmaxf(mx, vals[w]);
    }
    #pragma unroll
    for (int off = 16; off; off >>= 1)
        mx = fmaxf(mx, __shfl_xor_sync(0xffffffffu, mx, off));

    float sum = 0.f;
    #pragma unroll
    for (int w = 0; w < 7; w++) {
        int j = lane + 32 * w;
        if (j < NTOK) { vals[w] = expf(vals[w] - mx); sum += vals[w]; }
    }
    #pragma unroll
    for (int off = 16; off; off >>= 1)
        sum += __shfl_xor_sync(0xffffffffu, sum, off);

    float inv = 1.f / sum;
    #pragma unroll
    for (int w = 0; w < 7; w++) {
        int j = lane + 32 * w;
        if (j < NTOK) r[j] = vals[w] * inv;
    }
}

// o = P @ V, written as bf16 hi/lo split
__global__ void attn_av_kernel(const float* __restrict__ s, const float* __restrict__ qkv,
                               bf16* __restrict__ oh, bf16* __restrict__ ol)
{
    __shared__ float Ps[16][17], Vs[16][17];
    int bh = blockIdx.z;
    int b = bh / HEADS, hh = bh % HEADS;
    int tx = threadIdx.x, ty = threadIdx.y;
    int n = blockIdx.y * 16 + ty;
    int d = blockIdx.x * 16 + tx;

    float acc = 0.f;
    for (int mt = 0; mt < 13; mt++) {
        int mP = mt * 16 + tx;
        Ps[ty][tx] = (n < NTOK && mP < NTOK) ? s[((long)bh * NTOK + n) * NTOK + mP] : 0.f;
        int mV = mt * 16 + ty;
        Vs[ty][tx] = (mV < NTOK)
            ? qkv[((long)(b * NTOK + mV)) * QKVD + 2 * DIM + hh * DH + d] : 0.f;
        __syncthreads();
        #pragma unroll
        for (int kk = 0; kk < 16; kk++) acc += Ps[ty][kk] * Vs[kk][tx];
        __syncthreads();
    }
    if (n < NTOK) {
        bf16 h, lo; split2(acc, h, lo);
        long idx = ((long)(b * NTOK + n)) * DIM + hh * DH + d;
        oh[idx] = h; ol[idx] = lo;
    }
}

// ---------------- mean pool ----------------
__global__ void pool_kernel(const float* __restrict__ x, float* __restrict__ out)
{
    int b = blockIdx.x;
    for (int d = threadIdx.x; d < DIM; d += blockDim.x) {
        float s = 0.f;
        for (int n = 0; n < NTOK; n++)
            s += x[((long)(b * NTOK + n)) * DIM + d];
        out[b * DIM + d] = s * (1.f / NTOK);
    }
}

// ---------------- host ----------------
extern "C" void kernel_launch(void* const* d_in, const int* in_sizes, int n_in,
                              void* d_out, int out_size)
{
    const float* imgs    = (const float*)d_in[0];
    const float* patch_w = (const float*)d_in[1];
    const float* patch_b = (const float*)d_in[2];
    const float* cls     = (const float*)d_in[3];
    const float* pos     = (const float*)d_in[4];
    const float* ln1_g   = (const float*)d_in[5];
    const float* ln1_b   = (const float*)d_in[6];
    const float* wq      = (const float*)d_in[7];
    const float* bq      = (const float*)d_in[8];
    const float* wk      = (const float*)d_in[9];
    const float* bk      = (const float*)d_in[10];
    const float* wv      = (const float*)d_in[11];
    const float* bv      = (const float*)d_in[12];
    const float* wo      = (const float*)d_in[13];
    const float* bo      = (const float*)d_in[14];
    const float* ln2_g   = (const float*)d_in[15];
    const float* ln2_b   = (const float*)d_in[16];
    const float* w1      = (const float*)d_in[17];
    const float* b1      = (const float*)d_in[18];
    const float* w2      = (const float*)d_in[19];
    const float* b2      = (const float*)d_in[20];
    const float* hn_g    = (const float*)d_in[21];
    const float* hn_b    = (const float*)d_in[22];
    const float* hw      = (const float*)d_in[23];
    const float* hb      = (const float*)d_in[24];
    float* out = (float*)d_out;

    float *att, *x, *qkv, *bqkv, *pool, *pooln;
    bf16 *hh, *hl, *oh, *ol, *mh, *ml, *ph, *pl, *wth, *wtl, *wqh, *wql;
    bf16 *woh, *wol, *w1h, *w1l, *w2h, *w2l;
    cudaGetSymbolAddress((void**)&att,   g_att);
    cudaGetSymbolAddress((void**)&x,     g_x);
    cudaGetSymbolAddress((void**)&qkv,   g_qkv);
    cudaGetSymbolAddress((void**)&bqkv,  g_bqkv);
    cudaGetSymbolAddress((void**)&pool,  g_pool);
    cudaGetSymbolAddress((void**)&pooln, g_pooln);
    cudaGetSymbolAddress((void**)&hh,  g_hh);  cudaGetSymbolAddress((void**)&hl,  g_hl);
    cudaGetSymbolAddress((void**)&oh,  g_oh);  cudaGetSymbolAddress((void**)&ol,  g_ol);
    cudaGetSymbolAddress((void**)&mh,  g_mh);  cudaGetSymbolAddress((void**)&ml,  g_ml);
    cudaGetSymbolAddress((void**)&ph,  g_ph);  cudaGetSymbolAddress((void**)&pl,  g_pl);
    cudaGetSymbolAddress((void**)&wth, g_wth); cudaGetSymbolAddress((void**)&wtl, g_wtl);
    cudaGetSymbolAddress((void**)&wqh, g_wqh); cudaGetSymbolAddress((void**)&wql, g_wql);
    cudaGetSymbolAddress((void**)&woh, g_woh); cudaGetSymbolAddress((void**)&wol, g_wol);
    cudaGetSymbolAddress((void**)&w1h, g_w1h); cudaGetSymbolAddress((void**)&w1l, g_w1l);
    cudaGetSymbolAddress((void**)&w2h, g_w2h); cudaGetSymbolAddress((void**)&w2l, g_w2l);

    auto gemmS = [](const bf16* Ah, const bf16* Al, const bf16* Bh, const bf16* Bl,
                    const float* bias, const float* res, float* C, bf16* Ch, bf16* Cl,
                    int M, int N, int K, int mode) {
        dim3 grid(N / 128, (M + 127) / 128);
        gemm_bf16s<<<grid, 256>>>(Ah, Al, Bh, Bl, bias, res, C, Ch, Cl, M, N, K, mode);
    };

    // ---- patch embedding ----
    im2col_split_kernel<<<4096, 256>>>(imgs, ph, pl);
    transpose768_split_kernel<<<(DIM * DIM + 255) / 256, 256>>>(patch_w, wth, wtl);
    gemmS(ph, pl, wth, wtl, patch_b, nullptr, qkv, nullptr, nullptr, PTOK, DIM, DIM, 0);
    assemble_kernel<<<4096, 256>>>(qkv, cls, pos, x);

    // ---- transformer layers ----
    const int rows_sm = BATCH * HEADS * NTOK;
    for (int i = 0; i < LAYERS; i++) {
        qkv_pack_split_kernel<<<2048, 256>>>(wq + (long)i * DIM * DIM, wk + (long)i * DIM * DIM,
                                             wv + (long)i * DIM * DIM, bq + i * DIM,
                                             bk + i * DIM, bv + i * DIM, wqh, wql, bqkv);
        split_kernel<<<1024, 256>>>(wo + (long)i * DIM * DIM, woh, wol, DIM * DIM);
        split_kernel<<<2048, 256>>>(w1 + (long)i * DIM * MLPD, w1h, w1l, DIM * MLPD);
        split_kernel<<<2048, 256>>>(w2 + (long)i * MLPD * DIM, w2h, w2l, MLPD * DIM);

        ln_split_kernel<<<TOK, 256>>>(x, ln1_g + i * DIM, ln1_b + i * DIM, hh, hl);
        gemmS(hh, hl, wqh, wql, bqkv, nullptr, qkv, nullptr, nullptr, TOK, QKVD, DIM, 0);

        attn_scores_kernel<<<dim3(13, 13, BATCH * HEADS), dim3(16, 16)>>>(qkv, att);
        softmax_kernel<<<(rows_sm * 32 + 255) / 256, 256>>>(att, rows_sm);
        attn_av_kernel<<<dim3(4, 13, BATCH * HEADS), dim3(16, 16)>>>(att, qkv, oh, ol);

        gemmS(oh, ol, woh, wol, bo + i * DIM, x, x, nullptr, nullptr, TOK, DIM, DIM, 0);

        ln_split_kernel<<<TOK, 256>>>(x, ln2_g + i * DIM, ln2_b + i * DIM, hh, hl);
        gemmS(hh, hl, w1h, w1l, b1 + i * MLPD, nullptr, nullptr, mh, ml, TOK, MLPD, DIM, 1);
        gemmS(mh, ml, w2h, w2l, b2 + i * DIM, x, x, nullptr, nullptr, TOK, DIM, MLPD, 0);
    }

    // ---- head ----
    pool_kernel<<<BATCH, 256>>>(x, pool);
    ln_kernel<<<BATCH, 256>>>(pool, hn_g, hn_b, pooln);
    {
        dim3 grid((NC + 127) / 128, 1);
        sgemm128<<<grid, 256>>>(pooln, hw, hb, out, BATCH, NC, DIM);
    }
}